// round 4
// baseline (speedup 1.0000x reference)
#include <cuda_runtime.h>
#include <cstdint>

#define B_   16
#define C_   64
#define H_   80
#define W_   80
#define N_   32
#define HW_  (H_ * W_)
#define TOT_ (B_ * C_ * H_ * W_)

#define SPLIT_        5
#define SLICE_        (HW_ / SPLIT_)            // 1280 float4 per slice
#define ASSIGN_BLOCKS (B_ * N_ * SPLIT_)        // 2560
#define BG_           (B_ * N_)                 // 512
#define FOCAL_BLOCKS  1024
#define GRID_BLOCKS   (ASSIGN_BLOCKS + FOCAL_BLOCKS)
#define N4_           (TOT_ / 4)                // 409600 float4
#define FOCAL_CHUNK   (N4_ / FOCAL_BLOCKS)      // 400 float4 per block
#define ARRIVALS_PER_BATCH (N_ * SPLIT_)        // 160

// All slots written (or reset) every run -> graph-replay safe.
__device__ unsigned long long g_best[BG_];      // zero-init; reset by finisher
__device__ double g_focal_part[FOCAL_BLOCKS];
__device__ double g_pos_l1[B_];
__device__ double g_pos_gi[B_];
__device__ double g_pos_cf[B_];
__device__ int    g_pos_cnt[B_];
__device__ int    g_batch_done[B_];             // self-resetting
__device__ int    g_done = 0;                   // self-resetting

__device__ __forceinline__ float giou_f(float4 p, float4 q, float a2) {
    float a1 = (p.z - p.x) * (p.w - p.y);
    float ltx = fmaxf(p.x, q.x), lty = fmaxf(p.y, q.y);
    float rbx = fminf(p.z, q.z), rby = fminf(p.w, q.w);
    float wx = fmaxf(rbx - ltx, 0.0f), wy = fmaxf(rby - lty, 0.0f);
    float inter = wx * wy;
    float uni = a1 + a2 - inter;
    float iou = inter / uni;
    float ex = fminf(p.x, q.x), ey = fminf(p.y, q.y);
    float fx = fmaxf(p.z, q.z), fy = fmaxf(p.w, q.w);
    float ew = fmaxf(fx - ex, 0.0f), eh = fmaxf(fy - ey, 0.0f);
    float ae = ew * eh;
    return iou - (ae - uni) / ae;
}

__device__ __forceinline__ unsigned map_f(float f) {
    unsigned b = __float_as_uint(f);
    return b ^ (((int)b >> 31) | 0x80000000u);
}

__device__ __forceinline__ float focal_neg(float c) {
    // t = 0 term: 0.75 * p^2 * (-log(1-p))
    float p = fminf(fmaxf(c, 1e-6f), 1.0f - 1e-6f);
    return 0.75f * p * p * (-__logf(1.0f - p));
}

__device__ __forceinline__ float block_reduce_sum(float v, float* sh32) {
    int lane = threadIdx.x & 31;
    int wid  = threadIdx.x >> 5;
    #pragma unroll
    for (int o = 16; o > 0; o >>= 1) v += __shfl_down_sync(0xffffffffu, v, o);
    if (lane == 0) sh32[wid] = v;
    __syncthreads();
    v = (threadIdx.x < (blockDim.x >> 5)) ? sh32[lane] : 0.0f;
    if (wid == 0) {
        #pragma unroll
        for (int o = 16; o > 0; o >>= 1) v += __shfl_down_sync(0xffffffffu, v, o);
    }
    return v;
}

__global__ void __launch_bounds__(256, 5)
fused_kernel(const float* __restrict__ pred,
             const float* __restrict__ conf,
             const float* __restrict__ gtb,
             const int*   __restrict__ gtl,
             float* __restrict__ out) {
    __shared__ unsigned long long skey[32];
    __shared__ float sh32[32];
    int tid = threadIdx.x;
    int bid = blockIdx.x;

    if (bid < ASSIGN_BLOCKS) {
        // ---------------- assignment slice for (b, g) ----------------
        int bg = bid & (BG_ - 1);          // 512 = 2^9
        int slice = bid >> 9;              // 0..4
        int b = bg >> 5;
        int lab = gtl[bg];
        float4 gq = reinterpret_cast<const float4*>(gtb)[bg];
        float a2 = (gq.z - gq.x) * (gq.w - gq.y);
        const float4* pc = reinterpret_cast<const float4*>(pred)
                           + (size_t)(b * C_ + lab) * HW_ + slice * SLICE_;

        unsigned long long key = 0ull;
        int base = slice * SLICE_;
        #pragma unroll
        for (int k = 0; k < SLICE_ / 256; k++) {
            int idx = k * 256 + tid;
            float4 p = pc[idx];
            // intersection-only early out: any cell with GIoU > 0.3 has inter > 0,
            // and when the max is <= 0.3 the argmax index is unused.
            float wx = fminf(p.z, gq.z) - fmaxf(p.x, gq.x);
            float wy = fminf(p.w, gq.w) - fmaxf(p.y, gq.y);
            if (wx > 0.0f && wy > 0.0f) {
                float v = giou_f(p, gq, a2);
                unsigned long long nk = ((unsigned long long)map_f(v) << 32)
                                      | (0xFFFFFFFFu - (unsigned)(base + idx));
                key = (nk > key) ? nk : key;
            }
        }

        // block max-reduce of key
        int lane = tid & 31, wid = tid >> 5;
        #pragma unroll
        for (int o = 16; o > 0; o >>= 1) {
            unsigned long long other = __shfl_down_sync(0xffffffffu, key, o);
            key = (other > key) ? other : key;
        }
        if (lane == 0) skey[wid] = key;
        __syncthreads();
        if (wid == 0) {
            key = (lane < 8) ? skey[lane] : 0ull;
            #pragma unroll
            for (int o = 4; o > 0; o >>= 1) {
                unsigned long long other = __shfl_down_sync(0xffffffffu, key, o);
                key = (other > key) ? other : key;
            }
            if (lane == 0 && key) atomicMax(&g_best[bg], key);
        }

        // -------- per-batch arrival; 160th arrival runs the pos phase --------
        __shared__ int batch_last;
        __threadfence();
        __syncthreads();
        if (tid == 0) {
            int t = atomicAdd(&g_batch_done[b], 1);
            batch_last = (t == ARRIVALS_PER_BATCH - 1) ? 1 : 0;
        }
        __syncthreads();

        if (batch_last) {
            __threadfence();   // acquire
            __shared__ unsigned recs[N_];
            __shared__ float4   gbox[N_];
            if (tid < N_) {
                unsigned long long k2 =
                    ((volatile unsigned long long*)g_best)[b * N_ + tid];
                unsigned hi = (unsigned)(k2 >> 32);
                unsigned lo = (unsigned)k2;
                float v = (hi & 0x80000000u) ? __uint_as_float(hi ^ 0x80000000u)
                                             : __uint_as_float(~hi);
                unsigned idx = 0xFFFFFFFFu - lo;
                unsigned mi = (idx / W_) & 255u;
                unsigned mj = (idx % W_) & 255u;
                unsigned valid = (v > 0.3f) ? 1u : 0u;
                unsigned lb = (unsigned)gtl[b * N_ + tid] & 63u;
                recs[tid] = (valid << 30) | (lb << 16) | (mi << 8) | mj;
                gbox[tid] = reinterpret_cast<const float4*>(gtb)[b * N_ + tid];
                g_best[b * N_ + tid] = 0ull;      // reset for next replay
                if (tid == 0) g_batch_done[b] = 0;
            }
            __syncthreads();

            float sl1 = 0.0f, sgi = 0.0f, scf = 0.0f;
            int cnt = 0;
            #pragma unroll
            for (int half = 0; half < 2; half++) {
                int cell = (half << 8) + tid;       // 0..511
                int g = cell >> 4;
                int w = cell & 15;
                unsigned r = recs[g];
                int lab2 = (r >> 16) & 63;
                int mi  = (r >> 8) & 255;
                int mj  = r & 255;
                int i = mi - 2 + (w >> 2);
                int j = mj - 2 + (w & 3);
                bool act = ((r >> 30) & 1u) && ((unsigned)i < H_) && ((unsigned)j < W_);

                #pragma unroll
                for (int g2 = 0; g2 < N_; g2++) {
                    unsigned r2 = recs[g2];
                    int mi2 = (r2 >> 8) & 255;
                    int mj2 = r2 & 255;
                    bool cover = (g2 > g)
                               & (int)((r2 >> 30) & 1u)
                               & (((r2 ^ r) & 0x3F0000u) == 0u)
                               & ((unsigned)(i - mi2 + 2) < 4u)
                               & ((unsigned)(j - mj2 + 2) < 4u);
                    act &= !cover;
                }

                if (act) {
                    size_t off = (((size_t)b * C_ + lab2) * HW_ + (size_t)i * W_ + j);
                    float4 pb = reinterpret_cast<const float4*>(pred)[off];
                    float4 gq2 = gbox[g];
                    float a22 = (gq2.z - gq2.x) * (gq2.w - gq2.y);

                    sl1 += 0.25f * (fabsf(pb.x - gq2.x) + fabsf(pb.y - gq2.y) +
                                    fabsf(pb.z - gq2.z) + fabsf(pb.w - gq2.w));
                    sgi += 1.0f - giou_f(pb, gq2, a22);

                    float c = conf[off];
                    float p = fminf(fmaxf(c, 1e-6f), 1.0f - 1e-6f);
                    float f1 = 0.25f * (1.0f - p) * (1.0f - p) * (-__logf(p));
                    float f0 = 0.75f * p * p * (-__logf(1.0f - p));
                    scf += f1 - f0;
                    cnt += 1;
                }
            }

            float bl1 = block_reduce_sum(sl1, sh32);
            __syncthreads();
            float bgi = block_reduce_sum(sgi, sh32);
            __syncthreads();
            float bcf = block_reduce_sum(scf, sh32);
            __syncthreads();
            float bcnt = block_reduce_sum((float)cnt, sh32);
            if (tid == 0) {
                g_pos_l1[b]  = (double)bl1;
                g_pos_gi[b]  = (double)bgi;
                g_pos_cf[b]  = (double)bcf;
                g_pos_cnt[b] = (int)(bcnt + 0.5f);
            }
        }
    } else {
        // ---------------- dense focal (t = 0) partial ----------------
        int fb = bid - ASSIGN_BLOCKS;
        const float4* c4 = reinterpret_cast<const float4*>(conf);
        int start = fb * FOCAL_CHUNK;
        float acc = 0.0f;
        for (int i = start + tid; i < start + FOCAL_CHUNK; i += 256) {
            float4 v = c4[i];
            acc += focal_neg(v.x);
            acc += focal_neg(v.y);
            acc += focal_neg(v.z);
            acc += focal_neg(v.w);
        }
        float bsum = block_reduce_sum(acc, sh32);
        if (tid == 0) g_focal_part[fb] = (double)bsum;
    }

    // ---------------- global last-block finalize ----------------
    __shared__ int is_last;
    __threadfence();
    __syncthreads();
    if (tid == 0) {
        int t = atomicAdd(&g_done, 1);
        is_last = (t == GRID_BLOCKS - 1) ? 1 : 0;
    }
    __syncthreads();
    if (!is_last) return;
    __threadfence();   // acquire

    double l1 = 0.0, gi = 0.0, cf = 0.0;
    int np = 0;
    for (int k = tid; k < FOCAL_BLOCKS; k += 256) cf += g_focal_part[k];
    if (tid < B_) {
        l1 = g_pos_l1[tid];
        gi = g_pos_gi[tid];
        cf += g_pos_cf[tid];
        np = g_pos_cnt[tid];
    }

    __shared__ double sd[256];
    __shared__ int    sn[256];
    sd[tid] = l1; __syncthreads();
    for (int s = 128; s > 0; s >>= 1) { if (tid < s) sd[tid] += sd[tid + s]; __syncthreads(); }
    l1 = sd[0]; __syncthreads();
    sd[tid] = gi; __syncthreads();
    for (int s = 128; s > 0; s >>= 1) { if (tid < s) sd[tid] += sd[tid + s]; __syncthreads(); }
    gi = sd[0]; __syncthreads();
    sd[tid] = cf; __syncthreads();
    for (int s = 128; s > 0; s >>= 1) { if (tid < s) sd[tid] += sd[tid + s]; __syncthreads(); }
    cf = sd[0]; __syncthreads();
    sn[tid] = np; __syncthreads();
    for (int s = 128; s > 0; s >>= 1) { if (tid < s) sn[tid] += sn[tid + s]; __syncthreads(); }
    np = sn[0];

    if (tid == 0) {
        float denom = (float)(np > 1 ? np : 1);
        float fl1 = (float)l1 / denom;
        float fgi = (float)gi / denom;
        float fcf = (float)(cf / (double)TOT_);
        out[0] = fl1;
        out[1] = fgi;
        out[2] = fcf;
        out[3] = fl1 + 2.0f * fgi + fcf;
        out[4] = (float)np / (float)TOT_;
        g_done = 0;   // reset for next replay
    }
}

extern "C" void kernel_launch(void* const* d_in, const int* in_sizes, int n_in,
                              void* d_out, int out_size) {
    const float* pred = (const float*)d_in[0];   // [B,C,H,W,4]
    const float* conf = (const float*)d_in[1];   // [B,C,H,W]
    // d_in[2] = cam (unused by the loss)
    const float* gtb  = (const float*)d_in[3];   // [B,N,4]
    const int*   gtl  = (const int*)d_in[4];     // [B,N]
    float* out = (float*)d_out;

    fused_kernel<<<GRID_BLOCKS, 256>>>(pred, conf, gtb, gtl, out);
}